// round 2
// baseline (speedup 1.0000x reference)
#include <cuda_runtime.h>
#include <math.h>

#define B_SZ 2
#define N_SZ 512
#define EDIM 64
#define NDIM 256
#define HEADS 8
#define DH 32
#define SCALE_F 0.17677669529663687f  // 1/sqrt(32)

typedef unsigned long long ull;

// ---------------- scratch (device globals; no allocation allowed) ----------------
__device__ float g_qc[B_SZ * N_SZ * NDIM];  // nq + beq  (query-side constant per (b,i,c))
__device__ float g_kc[B_SZ * N_SZ * NDIM];  // nk + bek
__device__ float g_vc[B_SZ * N_SZ * NDIM];  // nv + bev

// ---------------- f32x2 helpers ----------------
__device__ __forceinline__ void ffma2(ull &acc, ull a, ull b) {
    asm("fma.rn.f32x2 %0, %1, %2, %0;" : "+l"(acc) : "l"(a), "l"(b));
}
__device__ __forceinline__ ull pack2(float lo, float hi) {
    ull r; asm("mov.b64 %0, {%1, %2};" : "=l"(r) : "f"(lo), "f"(hi)); return r;
}
__device__ __forceinline__ void unpack2(ull v, float &lo, float &hi) {
    asm("mov.b64 {%0, %1}, %2;" : "=f"(lo), "=f"(hi) : "l"(v));
}

// =================================================================================
// Kernel A: node projections.  qc = node@Wnq^T + (bnq+beq), kc = ..., vc = ...
// Grid: 64 CTAs x 256 threads. Each CTA does 16 node rows.
// smem: node_s[16][257] + wt[64][260] (transposed weight tile, k-major)
// =================================================================================
__global__ __launch_bounds__(256) void node_proj_kernel(
    const float* __restrict__ node,
    const float* __restrict__ Wnq, const float* __restrict__ bnq,
    const float* __restrict__ Wnk, const float* __restrict__ bnk,
    const float* __restrict__ Wnv, const float* __restrict__ bnv,
    const float* __restrict__ beq, const float* __restrict__ bek,
    const float* __restrict__ bev)
{
    extern __shared__ float smA[];
    float* node_s = smA;              // 16*257 = 4112 floats
    float* wt     = smA + 16 * 257;   // 64*260 = 16640 floats

    const int tid = threadIdx.x;
    const int r  = tid & 15;          // row within CTA block
    const int cg = tid >> 4;          // column group (16 cols each)
    const int r0 = blockIdx.x * 16;   // global row base (0..1023)

    // load 16 node rows (coalesced)
    for (int idx = tid; idx < 16 * 256; idx += 256) {
        int rr = idx >> 8, k = idx & 255;
        node_s[rr * 257 + k] = node[(r0 + rr) * 256 + k];
    }

    for (int p = 0; p < 3; p++) {
        const float* W  = (p == 0) ? Wnq : (p == 1) ? Wnk : Wnv;
        const float* b1 = (p == 0) ? bnq : (p == 1) ? bnk : bnv;
        const float* b2 = (p == 0) ? beq : (p == 1) ? bek : bev;
        float* dst = (p == 0) ? g_qc : (p == 1) ? g_kc : g_vc;

        float acc[16];
        #pragma unroll
        for (int q = 0; q < 16; q++) acc[q] = 0.f;

        for (int kt = 0; kt < 4; kt++) {
            __syncthreads();
            // stage W^T tile: wt[kk][c] = W[c][kt*64+kk]  (coalesced global reads)
            for (int idx = tid; idx < 64 * 256; idx += 256) {
                int c = idx >> 6, kk = idx & 63;
                wt[kk * 260 + c] = W[c * 256 + kt * 64 + kk];
            }
            __syncthreads();
            #pragma unroll 4
            for (int kk = 0; kk < 64; kk++) {
                float nv = node_s[r * 257 + kt * 64 + kk];
                const float* wrow = &wt[kk * 260 + cg * 16];
                float4 w0 = *(const float4*)(wrow);
                float4 w1 = *(const float4*)(wrow + 4);
                float4 w2 = *(const float4*)(wrow + 8);
                float4 w3 = *(const float4*)(wrow + 12);
                acc[0]  += w0.x * nv; acc[1]  += w0.y * nv; acc[2]  += w0.z * nv; acc[3]  += w0.w * nv;
                acc[4]  += w1.x * nv; acc[5]  += w1.y * nv; acc[6]  += w1.z * nv; acc[7]  += w1.w * nv;
                acc[8]  += w2.x * nv; acc[9]  += w2.y * nv; acc[10] += w2.z * nv; acc[11] += w2.w * nv;
                acc[12] += w3.x * nv; acc[13] += w3.y * nv; acc[14] += w3.z * nv; acc[15] += w3.w * nv;
            }
        }
        // add combined bias, write out
        int row = r0 + r;
        #pragma unroll
        for (int q4 = 0; q4 < 4; q4++) {
            float4 bb1 = *(const float4*)&b1[cg * 16 + q4 * 4];
            float4 bb2 = *(const float4*)&b2[cg * 16 + q4 * 4];
            float4 v;
            v.x = acc[q4 * 4 + 0] + bb1.x + bb2.x;
            v.y = acc[q4 * 4 + 1] + bb1.y + bb2.y;
            v.z = acc[q4 * 4 + 2] + bb1.z + bb2.z;
            v.w = acc[q4 * 4 + 3] + bb1.w + bb2.w;
            *(float4*)&dst[row * 256 + cg * 16 + q4 * 4] = v;
        }
    }
}

// =================================================================================
// Kernel B: fused attention over edges. One CTA per (b, i) = 1024 CTAs, 256 thr.
// Warp w == head h. Phase1: qk row (flash-free, full row fits smem). Softmax.
// Phase2: attention-weighted edge context + vc context. Epilogue: Wev matvec.
// =================================================================================
__global__ __launch_bounds__(256, 1) void main_attn_kernel(
    const float* __restrict__ edge,
    const float* __restrict__ Weq, const float* __restrict__ Wek,
    const float* __restrict__ Wev,
    float* __restrict__ out)
{
    extern __shared__ float sm[];
    float* sWq = sm;                  // 256*64 = 16384
    float* sWk = sWq + 16384;         // 16384
    float* sE  = sWk + 16384;         // 128*68 = 8704 (stride 68: 16B aligned, conflict-free)
    float* sQK = sE + 8704;           // 8*512 = 4096
    float* sQC = sQK + 4096;          // 256
    float* sOut = sQC + 256;          // 256
    // total 46080 floats = 184320 bytes

    const int i = blockIdx.x;
    const int b = blockIdx.y;
    const int tid = threadIdx.x;
    const int lane = tid & 31;
    const int h = tid >> 5;

    // stage Weq / Wek (row-major [256][64]; broadcast-read later, no padding needed)
    {
        const float4* gq = (const float4*)Weq;
        const float4* gk = (const float4*)Wek;
        float4* dq = (float4*)sWq;
        float4* dk = (float4*)sWk;
        for (int idx = tid; idx < 4096; idx += 256) { dq[idx] = gq[idx]; dk[idx] = gk[idx]; }
    }
    sQC[tid] = g_qc[(b * N_SZ + i) * NDIM + tid];

    const float* edgeRowBase = edge + (size_t)(b * N_SZ + i) * N_SZ * EDIM;

    // ---------------- Phase 1: qk[h][j] for all 512 j ----------------
    for (int tl = 0; tl < 4; tl++) {
        __syncthreads();
        {   // load edge tile [128][64] -> sE stride 68 (coalesced float4)
            const float4* src = (const float4*)(edgeRowBase + tl * 128 * EDIM);
            for (int idx = tid; idx < 128 * 16; idx += 256) {
                int j = idx >> 4, q = idx & 15;
                *(float4*)&sE[j * 68 + q * 4] = src[idx];
            }
        }
        __syncthreads();

        for (int js = 0; js < 128; js += 32) {
            const int jl = js + lane;
            const int jg = tl * 128 + jl;
            const float* kcRow = g_kc + (size_t)(b * N_SZ + jg) * NDIM + h * 32;
            float qk = 0.f;
            #pragma unroll
            for (int db = 0; db < 4; db++) {
                // prefetch kc for this d-block (consumed after the k loop)
                float kc8[8];
                *(float4*)&kc8[0] = *(const float4*)(kcRow + db * 8);
                *(float4*)&kc8[4] = *(const float4*)(kcRow + db * 8 + 4);

                ull aq[8], ak[8];
                #pragma unroll
                for (int dd = 0; dd < 8; dd++) {
                    aq[dd] = pack2(sQC[h * 32 + db * 8 + dd], 0.f);  // fold qc into acc
                    ak[dd] = pack2(kc8[dd], 0.f);                    // fold kc into acc
                }
                const int rowBase = (h * 32 + db * 8) * 64;
                #pragma unroll 4
                for (int k4 = 0; k4 < 16; k4++) {
                    ulonglong2 eP = *(const ulonglong2*)&sE[jl * 68 + k4 * 4];
                    #pragma unroll
                    for (int dd = 0; dd < 8; dd++) {
                        ulonglong2 wq = *(const ulonglong2*)&sWq[rowBase + dd * 64 + k4 * 4];
                        ffma2(aq[dd], wq.x, eP.x);
                        ffma2(aq[dd], wq.y, eP.y);
                        ulonglong2 wk = *(const ulonglong2*)&sWk[rowBase + dd * 64 + k4 * 4];
                        ffma2(ak[dd], wk.x, eP.x);
                        ffma2(ak[dd], wk.y, eP.y);
                    }
                }
                #pragma unroll
                for (int dd = 0; dd < 8; dd++) {
                    float ql, qh, kl, kh;
                    unpack2(aq[dd], ql, qh);
                    unpack2(ak[dd], kl, kh);
                    qk += (ql + qh) * (kl + kh);
                }
            }
            sQK[h * 512 + jg] = qk * SCALE_F;
        }
    }
    __syncthreads();

    // ---------------- Softmax (per warp = per head, unnormalized; keep sum) -----
    float* row = sQK + h * 512;
    float m = -1e30f;
    for (int jj = lane; jj < 512; jj += 32) m = fmaxf(m, row[jj]);
    #pragma unroll
    for (int off = 16; off > 0; off >>= 1) m = fmaxf(m, __shfl_xor_sync(0xffffffffu, m, off));
    float ssum = 0.f;
    for (int jj = lane; jj < 512; jj += 32) {
        float p = __expf(row[jj] - m);
        row[jj] = p;
        ssum += p;
    }
    #pragma unroll
    for (int off = 16; off > 0; off >>= 1) ssum += __shfl_xor_sync(0xffffffffu, ssum, off);

    // ---------------- Phase 2: ctx_e (64-dim edge ctx) + ctx_v (32-dim) ---------
    float ce0 = 0.f, ce1 = 0.f, cv = 0.f;  // lane holds ctx_e[2*lane], ctx_e[2*lane+1], ctx_v[lane]
    for (int tl = 0; tl < 4; tl++) {
        __syncthreads();
        {
            const float4* src = (const float4*)(edgeRowBase + tl * 128 * EDIM);
            for (int idx = tid; idx < 128 * 16; idx += 256) {
                int j = idx >> 4, q = idx & 15;
                *(float4*)&sE[j * 68 + q * 4] = src[idx];
            }
        }
        __syncthreads();
        const float* vcBase = g_vc + (size_t)(b * N_SZ + tl * 128) * NDIM + h * 32 + lane;
        #pragma unroll 4
        for (int jlp = 0; jlp < 128; jlp++) {
            float a = row[tl * 128 + jlp];
            float2 ev = *(const float2*)&sE[jlp * 68 + 2 * lane];
            ce0 += a * ev.x;
            ce1 += a * ev.y;
            cv  += a * vcBase[jlp * 256];
        }
    }

    // ---------------- Epilogue: out[c] = (Wev[c,:]·ctx_e + ctx_v[d]) / ssum -----
    float inv = 1.f / ssum;
    #pragma unroll 4
    for (int dd = 0; dd < 32; dd++) {
        int c = h * 32 + dd;
        float2 w2 = *(const float2*)&Wev[c * 64 + 2 * lane];  // coalesced per warp
        float part = w2.x * ce0 + w2.y * ce1;
        #pragma unroll
        for (int off = 16; off > 0; off >>= 1) part += __shfl_xor_sync(0xffffffffu, part, off);
        float cvd = __shfl_sync(0xffffffffu, cv, dd);
        if (lane == 0) sOut[c] = (part + cvd) * inv;
    }
    __syncthreads();
    out[(size_t)(b * N_SZ + i) * NDIM + tid] = sOut[tid];
}

// =================================================================================
extern "C" void kernel_launch(void* const* d_in, const int* in_sizes, int n_in,
                              void* d_out, int out_size)
{
    const float* node = (const float*)d_in[0];
    const float* edge = (const float*)d_in[1];
    const float* Wnq  = (const float*)d_in[2];
    const float* bnq  = (const float*)d_in[3];
    const float* Wnk  = (const float*)d_in[4];
    const float* bnk  = (const float*)d_in[5];
    const float* Wnv  = (const float*)d_in[6];
    const float* bnv  = (const float*)d_in[7];
    const float* Weq  = (const float*)d_in[8];
    const float* beq  = (const float*)d_in[9];
    const float* Wek  = (const float*)d_in[10];
    const float* bek  = (const float*)d_in[11];
    const float* Wev  = (const float*)d_in[12];
    const float* bev  = (const float*)d_in[13];
    float* out = (float*)d_out;

    const int smemA = (16 * 257 + 64 * 260) * 4;     // 83008 B
    const int smemB = 46080 * 4;                     // 184320 B
    cudaFuncSetAttribute(node_proj_kernel, cudaFuncAttributeMaxDynamicSharedMemorySize, smemA);
    cudaFuncSetAttribute(main_attn_kernel, cudaFuncAttributeMaxDynamicSharedMemorySize, smemB);

    node_proj_kernel<<<64, 256, smemA>>>(node, Wnq, bnq, Wnk, bnk, Wnv, bnv, beq, bek, bev);

    dim3 grid(N_SZ, B_SZ);
    main_attn_kernel<<<grid, 256, smemB>>>(edge, Weq, Wek, Wev, out);
}

// round 3
// speedup vs baseline: 2.3812x; 2.3812x over previous
#include <cuda_runtime.h>
#include <math.h>

#define B_SZ 2
#define N_SZ 512
#define EDIM 64
#define NDIM 256
#define HEADS 8
#define DH 32
#define SCALE_F 0.17677669529663687f  // 1/sqrt(32)

// ---------------- scratch (device globals; no allocation allowed) ----------------
__device__ float g_qc[B_SZ * N_SZ * NDIM];  // nq + beq
__device__ float g_kc[B_SZ * N_SZ * NDIM];  // nk + bek
__device__ float g_vc[B_SZ * N_SZ * NDIM];  // nv + bev

// ---------------- tf32 helpers ----------------
__device__ __forceinline__ unsigned f2tf(float f) {
    unsigned u; asm("cvt.rna.tf32.f32 %0, %1;" : "=r"(u) : "f"(f)); return u;
}
__device__ __forceinline__ void mma_tf32(float* d, const unsigned* a, const unsigned* b) {
    asm("mma.sync.aligned.m16n8k8.row.col.f32.tf32.tf32.f32 "
        "{%0,%1,%2,%3}, {%4,%5,%6,%7}, {%8,%9}, {%0,%1,%2,%3};"
        : "+f"(d[0]), "+f"(d[1]), "+f"(d[2]), "+f"(d[3])
        : "r"(a[0]), "r"(a[1]), "r"(a[2]), "r"(a[3]), "r"(b[0]), "r"(b[1]));
}

// =================================================================================
// Kernel A: node projections.  qc = node@Wnq^T + (bnq+beq), etc.  (unchanged, works)
// =================================================================================
__global__ __launch_bounds__(256) void node_proj_kernel(
    const float* __restrict__ node,
    const float* __restrict__ Wnq, const float* __restrict__ bnq,
    const float* __restrict__ Wnk, const float* __restrict__ bnk,
    const float* __restrict__ Wnv, const float* __restrict__ bnv,
    const float* __restrict__ beq, const float* __restrict__ bek,
    const float* __restrict__ bev)
{
    extern __shared__ float smA[];
    float* node_s = smA;              // 16*257
    float* wt     = smA + 16 * 257;   // 64*260

    const int tid = threadIdx.x;
    const int r  = tid & 15;
    const int cg = tid >> 4;
    const int r0 = blockIdx.x * 16;

    for (int idx = tid; idx < 16 * 256; idx += 256) {
        int rr = idx >> 8, k = idx & 255;
        node_s[rr * 257 + k] = node[(r0 + rr) * 256 + k];
    }

    for (int p = 0; p < 3; p++) {
        const float* W  = (p == 0) ? Wnq : (p == 1) ? Wnk : Wnv;
        const float* b1 = (p == 0) ? bnq : (p == 1) ? bnk : bnv;
        const float* b2 = (p == 0) ? beq : (p == 1) ? bek : bev;
        float* dst = (p == 0) ? g_qc : (p == 1) ? g_kc : g_vc;

        float acc[16];
        #pragma unroll
        for (int q = 0; q < 16; q++) acc[q] = 0.f;

        for (int kt = 0; kt < 4; kt++) {
            __syncthreads();
            for (int idx = tid; idx < 64 * 256; idx += 256) {
                int c = idx >> 6, kk = idx & 63;
                wt[kk * 260 + c] = W[c * 256 + kt * 64 + kk];
            }
            __syncthreads();
            #pragma unroll 4
            for (int kk = 0; kk < 64; kk++) {
                float nv = node_s[r * 257 + kt * 64 + kk];
                const float* wrow = &wt[kk * 260 + cg * 16];
                float4 w0 = *(const float4*)(wrow);
                float4 w1 = *(const float4*)(wrow + 4);
                float4 w2 = *(const float4*)(wrow + 8);
                float4 w3 = *(const float4*)(wrow + 12);
                acc[0]  += w0.x * nv; acc[1]  += w0.y * nv; acc[2]  += w0.z * nv; acc[3]  += w0.w * nv;
                acc[4]  += w1.x * nv; acc[5]  += w1.y * nv; acc[6]  += w1.z * nv; acc[7]  += w1.w * nv;
                acc[8]  += w2.x * nv; acc[9]  += w2.y * nv; acc[10] += w2.z * nv; acc[11] += w2.w * nv;
                acc[12] += w3.x * nv; acc[13] += w3.y * nv; acc[14] += w3.z * nv; acc[15] += w3.w * nv;
            }
        }
        int row = r0 + r;
        #pragma unroll
        for (int q4 = 0; q4 < 4; q4++) {
            float4 bb1 = *(const float4*)&b1[cg * 16 + q4 * 4];
            float4 bb2 = *(const float4*)&b2[cg * 16 + q4 * 4];
            float4 v;
            v.x = acc[q4 * 4 + 0] + bb1.x + bb2.x;
            v.y = acc[q4 * 4 + 1] + bb1.y + bb2.y;
            v.z = acc[q4 * 4 + 2] + bb1.z + bb2.z;
            v.w = acc[q4 * 4 + 3] + bb1.w + bb2.w;
            *(float4*)&dst[row * 256 + cg * 16 + q4 * 4] = v;
        }
    }
}

// =================================================================================
// Kernel B: fused attention. CTA = (b,i). Warp = head. Phase 1 on tensor cores
// (mma.sync tf32): per j-tile of 32, EQ/EK fragments computed and combined in-reg.
// =================================================================================
__global__ __launch_bounds__(256, 1) void main_attn_kernel(
    const float* __restrict__ edge,
    const float* __restrict__ Weq, const float* __restrict__ Wek,
    const float* __restrict__ Wev,
    float* __restrict__ out)
{
    extern __shared__ float sm[];
    float* sWq = sm;                    // 256*68 = 17408 (tf32 bits)
    float* sWk = sWq + 17408;           // 17408 (tf32 bits)
    float* sE  = sWk + 17408;           // 32*68 = 2176 (tf32 bits) [phase2: 128*68 alias]
    float* sKC = sE + 2176;             // 32*260 = 8320 (fp32)
    float* sQK = sKC + 8320;            // 8*512 = 4096
    float* sQC = sQK + 4096;            // 256
    float* sOut = sQC + 256;            // 256
    // total 49920 floats = 199680 bytes

    const int i = blockIdx.x;
    const int b = blockIdx.y;
    const int tid = threadIdx.x;
    const int lane = tid & 31;
    const int h = tid >> 5;
    const int g = lane >> 2;   // mma groupID
    const int c = lane & 3;

    // ---- stage weights (tf32-converted) into conflict-free stride-68 layout ----
    for (int idx4 = tid; idx4 < 4096; idx4 += 256) {
        int row = idx4 >> 4, q = idx4 & 15;
        float4 wq = *(const float4*)(Weq + idx4 * 4);
        float4 wk = *(const float4*)(Wek + idx4 * 4);
        unsigned* dq = (unsigned*)&sWq[row * 68 + q * 4];
        unsigned* dk = (unsigned*)&sWk[row * 68 + q * 4];
        dq[0] = f2tf(wq.x); dq[1] = f2tf(wq.y); dq[2] = f2tf(wq.z); dq[3] = f2tf(wq.w);
        dk[0] = f2tf(wk.x); dk[1] = f2tf(wk.y); dk[2] = f2tf(wk.z); dk[3] = f2tf(wk.w);
    }
    sQC[tid] = g_qc[(b * N_SZ + i) * NDIM + tid];

    const float* edgeRowBase = edge + (size_t)(b * N_SZ + i) * N_SZ * EDIM;
    const float* kcBase = g_kc + (size_t)b * N_SZ * NDIM;

    // ---------------- Phase 1: qk via tensor cores ----------------
    for (int jt = 0; jt < 16; jt++) {
        __syncthreads();
        // stage edge tile [32 j][64 k] (tf32) — 2 float4 per thread
        {
            const float4* src = (const float4*)(edgeRowBase + jt * 32 * EDIM);
            #pragma unroll
            for (int t = 0; t < 2; t++) {
                int idx = tid + t * 256;
                int row = idx >> 4, q = idx & 15;
                float4 e4 = src[idx];
                unsigned* de = (unsigned*)&sE[row * 68 + q * 4];
                de[0] = f2tf(e4.x); de[1] = f2tf(e4.y); de[2] = f2tf(e4.z); de[3] = f2tf(e4.w);
            }
        }
        // stage kc tile [32 j][256 ch] fp32 — 8 float4 per thread
        {
            const float4* src = (const float4*)(kcBase + jt * 32 * NDIM);
            #pragma unroll
            for (int t = 0; t < 8; t++) {
                int idx = tid + t * 256;
                int row = idx >> 6, q = idx & 63;
                *(float4*)&sKC[row * 260 + q * 4] = src[idx];
            }
        }
        __syncthreads();

        // load all A fragments (edge tile), conflict-free
        unsigned aA[2][8][4];
        const unsigned* eb = (const unsigned*)sE;
        #pragma unroll
        for (int mi = 0; mi < 2; mi++) {
            int r0 = mi * 16 + g;
            #pragma unroll
            for (int k = 0; k < 8; k++) {
                aA[mi][k][0] = eb[r0 * 68 + k * 8 + c];
                aA[mi][k][1] = eb[(r0 + 8) * 68 + k * 8 + c];
                aA[mi][k][2] = eb[r0 * 68 + k * 8 + c + 4];
                aA[mi][k][3] = eb[(r0 + 8) * 68 + k * 8 + c + 4];
            }
        }

        float Dq[2][4][4], Dk[2][4][4];
        #pragma unroll
        for (int mi = 0; mi < 2; mi++)
            #pragma unroll
            for (int ni = 0; ni < 4; ni++)
                #pragma unroll
                for (int e = 0; e < 4; e++) { Dq[mi][ni][e] = 0.f; Dk[mi][ni][e] = 0.f; }

        // EQ = E @ Wq_h^T
        {
            const unsigned* W = (const unsigned*)sWq;
            #pragma unroll
            for (int ni = 0; ni < 4; ni++) {
                int wrow = h * 32 + ni * 8 + g;
                unsigned Bf[8][2];
                #pragma unroll
                for (int k = 0; k < 8; k++) {
                    Bf[k][0] = W[wrow * 68 + k * 8 + c];
                    Bf[k][1] = W[wrow * 68 + k * 8 + c + 4];
                }
                #pragma unroll
                for (int k = 0; k < 8; k++) {
                    mma_tf32(Dq[0][ni], aA[0][k], Bf[k]);
                    mma_tf32(Dq[1][ni], aA[1][k], Bf[k]);
                }
            }
        }
        // EK = E @ Wk_h^T
        {
            const unsigned* W = (const unsigned*)sWk;
            #pragma unroll
            for (int ni = 0; ni < 4; ni++) {
                int wrow = h * 32 + ni * 8 + g;
                unsigned Bf[8][2];
                #pragma unroll
                for (int k = 0; k < 8; k++) {
                    Bf[k][0] = W[wrow * 68 + k * 8 + c];
                    Bf[k][1] = W[wrow * 68 + k * 8 + c + 4];
                }
                #pragma unroll
                for (int k = 0; k < 8; k++) {
                    mma_tf32(Dk[0][ni], aA[0][k], Bf[k]);
                    mma_tf32(Dk[1][ni], aA[1][k], Bf[k]);
                }
            }
        }

        // combine: qk[j] = sum_d (EQ+qc)(EK+kc)
        float acc[4] = {0.f, 0.f, 0.f, 0.f};
        #pragma unroll
        for (int mi = 0; mi < 2; mi++) {
            int r0 = mi * 16 + g, r1 = r0 + 8;
            #pragma unroll
            for (int ni = 0; ni < 4; ni++) {
                int ch = h * 32 + ni * 8 + 2 * c;
                float q0 = sQC[ch], q1 = sQC[ch + 1];
                float k00 = sKC[r0 * 260 + ch], k01 = sKC[r0 * 260 + ch + 1];
                float k10 = sKC[r1 * 260 + ch], k11 = sKC[r1 * 260 + ch + 1];
                acc[mi * 2]     += (Dq[mi][ni][0] + q0) * (Dk[mi][ni][0] + k00)
                                 + (Dq[mi][ni][1] + q1) * (Dk[mi][ni][1] + k01);
                acc[mi * 2 + 1] += (Dq[mi][ni][2] + q0) * (Dk[mi][ni][2] + k10)
                                 + (Dq[mi][ni][3] + q1) * (Dk[mi][ni][3] + k11);
            }
        }
        #pragma unroll
        for (int t = 1; t <= 2; t <<= 1) {
            acc[0] += __shfl_xor_sync(0xffffffffu, acc[0], t);
            acc[1] += __shfl_xor_sync(0xffffffffu, acc[1], t);
            acc[2] += __shfl_xor_sync(0xffffffffu, acc[2], t);
            acc[3] += __shfl_xor_sync(0xffffffffu, acc[3], t);
        }
        if (c == 0) {
            int jb = jt * 32;
            sQK[h * 512 + jb + g]          = acc[0] * SCALE_F;
            sQK[h * 512 + jb + g + 8]      = acc[1] * SCALE_F;
            sQK[h * 512 + jb + 16 + g]     = acc[2] * SCALE_F;
            sQK[h * 512 + jb + 24 + g]     = acc[3] * SCALE_F;
        }
    }
    __syncthreads();

    // ---------------- Softmax (per warp = per head, unnormalized) ----------------
    float* row = sQK + h * 512;
    float m = -1e30f;
    for (int jj = lane; jj < 512; jj += 32) m = fmaxf(m, row[jj]);
    #pragma unroll
    for (int off = 16; off > 0; off >>= 1) m = fmaxf(m, __shfl_xor_sync(0xffffffffu, m, off));
    float ssum = 0.f;
    for (int jj = lane; jj < 512; jj += 32) {
        float p = __expf(row[jj] - m);
        row[jj] = p;
        ssum += p;
    }
    #pragma unroll
    for (int off = 16; off > 0; off >>= 1) ssum += __shfl_xor_sync(0xffffffffu, ssum, off);

    // ---------------- Phase 2: weighted edge context + vc context ----------------
    float* sE2 = sE;  // reuse sE+sKC region: 128*68 = 8704 <= 10496
    float ce0 = 0.f, ce1 = 0.f, cv = 0.f;
    for (int tl = 0; tl < 4; tl++) {
        __syncthreads();
        {
            const float4* src = (const float4*)(edgeRowBase + tl * 128 * EDIM);
            for (int idx = tid; idx < 128 * 16; idx += 256) {
                int j = idx >> 4, q = idx & 15;
                *(float4*)&sE2[j * 68 + q * 4] = src[idx];
            }
        }
        __syncthreads();
        const float* vcBase = g_vc + (size_t)(b * N_SZ + tl * 128) * NDIM + h * 32 + lane;
        #pragma unroll 4
        for (int jlp = 0; jlp < 128; jlp++) {
            float a = row[tl * 128 + jlp];
            float2 ev = *(const float2*)&sE2[jlp * 68 + 2 * lane];
            ce0 += a * ev.x;
            ce1 += a * ev.y;
            cv  += a * vcBase[jlp * 256];
        }
    }

    // ---------------- Epilogue: out[c] = (Wev[c,:]·ctx_e + ctx_v[d]) / ssum ------
    float inv = 1.f / ssum;
    #pragma unroll 4
    for (int dd = 0; dd < 32; dd++) {
        int ch = h * 32 + dd;
        float2 w2 = *(const float2*)&Wev[ch * 64 + 2 * lane];
        float part = w2.x * ce0 + w2.y * ce1;
        #pragma unroll
        for (int off = 16; off > 0; off >>= 1) part += __shfl_xor_sync(0xffffffffu, part, off);
        float cvd = __shfl_sync(0xffffffffu, cv, dd);
        if (lane == 0) sOut[ch] = (part + cvd) * inv;
    }
    __syncthreads();
    out[(size_t)(b * N_SZ + i) * NDIM + tid] = sOut[tid];
}

// =================================================================================
extern "C" void kernel_launch(void* const* d_in, const int* in_sizes, int n_in,
                              void* d_out, int out_size)
{
    const float* node = (const float*)d_in[0];
    const float* edge = (const float*)d_in[1];
    const float* Wnq  = (const float*)d_in[2];
    const float* bnq  = (const float*)d_in[3];
    const float* Wnk  = (const float*)d_in[4];
    const float* bnk  = (const float*)d_in[5];
    const float* Wnv  = (const float*)d_in[6];
    const float* bnv  = (const float*)d_in[7];
    const float* Weq  = (const float*)d_in[8];
    const float* beq  = (const float*)d_in[9];
    const float* Wek  = (const float*)d_in[10];
    const float* bek  = (const float*)d_in[11];
    const float* Wev  = (const float*)d_in[12];
    const float* bev  = (const float*)d_in[13];
    float* out = (float*)d_out;

    const int smemA = (16 * 257 + 64 * 260) * 4;     // 83008 B
    const int smemB = 49920 * 4;                     // 199680 B
    cudaFuncSetAttribute(node_proj_kernel, cudaFuncAttributeMaxDynamicSharedMemorySize, smemA);
    cudaFuncSetAttribute(main_attn_kernel, cudaFuncAttributeMaxDynamicSharedMemorySize, smemB);

    node_proj_kernel<<<64, 256, smemA>>>(node, Wnq, bnq, Wnk, bnk, Wnv, bnv, beq, bek, bev);

    dim3 grid(N_SZ, B_SZ);
    main_attn_kernel<<<grid, 256, smemB>>>(edge, Weq, Wek, Wev, out);
}

// round 4
// speedup vs baseline: 3.6473x; 1.5317x over previous
#include <cuda_runtime.h>
#include <math.h>

#define B_SZ 2
#define N_SZ 512
#define EDIM 64
#define NDIM 256
#define HEADS 8
#define DH 32
#define SCALE_F 0.17677669529663687f  // 1/sqrt(32)

// ---------------- scratch (device globals; no allocation allowed) ----------------
__device__ float g_qc[B_SZ * N_SZ * NDIM];  // nq + beq
__device__ float g_kc[B_SZ * N_SZ * NDIM];  // nk + bek
__device__ float g_vc[B_SZ * N_SZ * NDIM];  // nv + bev

// ---------------- helpers ----------------
__device__ __forceinline__ unsigned f2tf(float f) {
    unsigned u; asm("cvt.rna.tf32.f32 %0, %1;" : "=r"(u) : "f"(f)); return u;
}
__device__ __forceinline__ void mma_tf32(float* d, const unsigned* a, const unsigned* b) {
    asm("mma.sync.aligned.m16n8k8.row.col.f32.tf32.tf32.f32 "
        "{%0,%1,%2,%3}, {%4,%5,%6,%7}, {%8,%9}, {%0,%1,%2,%3};"
        : "+f"(d[0]), "+f"(d[1]), "+f"(d[2]), "+f"(d[3])
        : "r"(a[0]), "r"(a[1]), "r"(a[2]), "r"(a[3]), "r"(b[0]), "r"(b[1]));
}
__device__ __forceinline__ void cp_async16(void* smem_dst, const void* gsrc) {
    unsigned s = (unsigned)__cvta_generic_to_shared(smem_dst);
    asm volatile("cp.async.cg.shared.global [%0], [%1], 16;" :: "r"(s), "l"(gsrc));
}

// =================================================================================
// Kernel A: node projections.  grid (128, 3) — blockIdx.y selects projection.
// Each CTA: 8 node rows x 256 output cols.
// =================================================================================
__global__ __launch_bounds__(256) void node_proj_kernel(
    const float* __restrict__ node,
    const float* __restrict__ Wnq, const float* __restrict__ bnq,
    const float* __restrict__ Wnk, const float* __restrict__ bnk,
    const float* __restrict__ Wnv, const float* __restrict__ bnv,
    const float* __restrict__ beq, const float* __restrict__ bek,
    const float* __restrict__ bev)
{
    extern __shared__ float smA[];
    float* node_s = smA;             // 8*257 = 2056
    float* wt     = smA + 8 * 257;   // 64*260 = 16640

    const int tid = threadIdx.x;
    const int r  = tid & 7;          // row within CTA block
    const int cg = tid >> 3;         // col group (8 cols each, 32 groups)
    const int r0 = blockIdx.x * 8;
    const int p  = blockIdx.y;

    const float* W  = (p == 0) ? Wnq : (p == 1) ? Wnk : Wnv;
    const float* b1 = (p == 0) ? bnq : (p == 1) ? bnk : bnv;
    const float* b2 = (p == 0) ? beq : (p == 1) ? bek : bev;
    float* dst = (p == 0) ? g_qc : (p == 1) ? g_kc : g_vc;

    for (int idx = tid; idx < 8 * 256; idx += 256) {
        int rr = idx >> 8, k = idx & 255;
        node_s[rr * 257 + k] = node[(r0 + rr) * 256 + k];
    }

    float acc[8];
    #pragma unroll
    for (int q = 0; q < 8; q++) acc[q] = 0.f;

    for (int kt = 0; kt < 4; kt++) {
        __syncthreads();
        for (int idx = tid; idx < 64 * 256; idx += 256) {
            int c = idx >> 6, kk = idx & 63;
            wt[kk * 260 + c] = W[c * 256 + kt * 64 + kk];
        }
        __syncthreads();
        #pragma unroll 4
        for (int kk = 0; kk < 64; kk++) {
            float nv = node_s[r * 257 + kt * 64 + kk];
            const float* wrow = &wt[kk * 260 + cg * 8];
            float4 w0 = *(const float4*)(wrow);
            float4 w1 = *(const float4*)(wrow + 4);
            acc[0] += w0.x * nv; acc[1] += w0.y * nv; acc[2] += w0.z * nv; acc[3] += w0.w * nv;
            acc[4] += w1.x * nv; acc[5] += w1.y * nv; acc[6] += w1.z * nv; acc[7] += w1.w * nv;
        }
    }
    int row = r0 + r;
    #pragma unroll
    for (int q4 = 0; q4 < 2; q4++) {
        float4 bb1 = *(const float4*)&b1[cg * 8 + q4 * 4];
        float4 bb2 = *(const float4*)&b2[cg * 8 + q4 * 4];
        float4 v;
        v.x = acc[q4 * 4 + 0] + bb1.x + bb2.x;
        v.y = acc[q4 * 4 + 1] + bb1.y + bb2.y;
        v.z = acc[q4 * 4 + 2] + bb1.z + bb2.z;
        v.w = acc[q4 * 4 + 3] + bb1.w + bb2.w;
        *(float4*)&dst[row * 256 + cg * 8 + q4 * 4] = v;
    }
}

// =================================================================================
// Kernel B: fused attention. CTA = (b,i), 512 threads = 16 warps.
// warp -> (s = wid>>3 j-half, h = wid&7 head).
// Phase 1: tf32 mma with cp.async triple-buffered edge tiles (64 j per tile;
//          s=0 takes rows [0,32), s=1 rows [32,64) of the tile).
// Softmax split across halves. Phase 2 split across halves.
// =================================================================================
__global__ __launch_bounds__(512, 1) void main_attn_kernel(
    const float* __restrict__ edge,
    const float* __restrict__ Weq, const float* __restrict__ Wek,
    const float* __restrict__ Wev,
    float* __restrict__ out)
{
    extern __shared__ float sm[];
    float* sWq = sm;                    // 17408 (tf32 bits)    | phase2: sE2 2x8704
    float* sWk = sm + 17408;            // 17408 (tf32 bits)
    float* sE  = sm + 34816;            // 3 x 4352 (raw fp32 edge tiles)
    float* sQK = sm + 47872;            // 8*512 = 4096
    float* sQC = sm + 51968;            // 256
    float* sOut = sm + 52224;           // 256
    float* sMax = sm + 52480;           // 16
    float* sSum = sm + 52496;           // 16
    float* sP   = sm + 52512;           // 768 (phase-2 partials)
    // total 53504 floats = 214016 bytes

    const int i = blockIdx.x;
    const int b = blockIdx.y;
    const int tid = threadIdx.x;
    const int lane = tid & 31;
    const int wid = tid >> 5;
    const int h = wid & 7;
    const int s = wid >> 3;
    const int g = lane >> 2;   // mma groupID
    const int c = lane & 3;

    const int bN = b * N_SZ;
    const float* edgeRowBase = edge + (size_t)(bN + i) * N_SZ * EDIM;

    // ---- prologue: start cp.async of edge tile 0 into buffer 0 ----
    {
        const float4* src = (const float4*)(edgeRowBase);
        float* dstb = sE;
        #pragma unroll
        for (int u = 0; u < 2; u++) {
            int idx = tid + u * 512;
            int row = idx >> 4, q = idx & 15;
            cp_async16(dstb + row * 68 + q * 4, src + idx);
        }
        asm volatile("cp.async.commit_group;");
    }

    // ---- stage weights (tf32-converted, stride-68 conflict-free) ----
    for (int idx4 = tid; idx4 < 4096; idx4 += 512) {
        int row = idx4 >> 4, q = idx4 & 15;
        float4 wq = *(const float4*)(Weq + idx4 * 4);
        float4 wk = *(const float4*)(Wek + idx4 * 4);
        unsigned* dq = (unsigned*)&sWq[row * 68 + q * 4];
        unsigned* dk = (unsigned*)&sWk[row * 68 + q * 4];
        dq[0] = f2tf(wq.x); dq[1] = f2tf(wq.y); dq[2] = f2tf(wq.z); dq[3] = f2tf(wq.w);
        dk[0] = f2tf(wk.x); dk[1] = f2tf(wk.y); dk[2] = f2tf(wk.z); dk[3] = f2tf(wk.w);
    }
    if (tid < 256) sQC[tid] = g_qc[(bN + i) * NDIM + tid];

    const unsigned* uWq = (const unsigned*)sWq;
    const unsigned* uWk = (const unsigned*)sWk;

    // ---------------- Phase 1: qk via tensor cores, pipelined tiles ----------------
    for (int jt = 0; jt < 8; jt++) {
        // prefetch next tile (depth-1, triple buffer)
        if (jt < 7) {
            const float4* src = (const float4*)(edgeRowBase + (jt + 1) * 64 * EDIM);
            float* dstb = sE + ((jt + 1) % 3) * 4352;
            #pragma unroll
            for (int u = 0; u < 2; u++) {
                int idx = tid + u * 512;
                int row = idx >> 4, q = idx & 15;
                cp_async16(dstb + row * 68 + q * 4, src + idx);
            }
            asm volatile("cp.async.commit_group;");
            asm volatile("cp.async.wait_group 1;");
        } else {
            asm volatile("cp.async.wait_group 0;");
        }
        __syncthreads();

        const unsigned* eb = (const unsigned*)(sE + (jt % 3) * 4352) + s * 32 * 68;

        float Dq[2][4][4], Dk[2][4][4];
        #pragma unroll
        for (int mi = 0; mi < 2; mi++)
            #pragma unroll
            for (int ni = 0; ni < 4; ni++)
                #pragma unroll
                for (int e = 0; e < 4; e++) { Dq[mi][ni][e] = 0.f; Dk[mi][ni][e] = 0.f; }

        #pragma unroll
        for (int k = 0; k < 8; k++) {
            unsigned a0[4], a1[4];
            a0[0] = eb[g * 68 + k * 8 + c];         a0[1] = eb[(g + 8) * 68 + k * 8 + c];
            a0[2] = eb[g * 68 + k * 8 + c + 4];     a0[3] = eb[(g + 8) * 68 + k * 8 + c + 4];
            a1[0] = eb[(16 + g) * 68 + k * 8 + c];  a1[1] = eb[(24 + g) * 68 + k * 8 + c];
            a1[2] = eb[(16 + g) * 68 + k * 8 + c + 4]; a1[3] = eb[(24 + g) * 68 + k * 8 + c + 4];
            #pragma unroll
            for (int ni = 0; ni < 4; ni++) {
                const int woff = (h * 32 + ni * 8 + g) * 68 + k * 8 + c;
                unsigned bq[2] = { uWq[woff], uWq[woff + 4] };
                unsigned bk[2] = { uWk[woff], uWk[woff + 4] };
                mma_tf32(Dq[0][ni], a0, bq);
                mma_tf32(Dq[1][ni], a1, bq);
                mma_tf32(Dk[0][ni], a0, bk);
                mma_tf32(Dk[1][ni], a1, bk);
            }
        }

        // combine: qk[j] = sum_d (EQ+qc)(EK+kc)    (kc direct from gmem/L2)
        const int jg0 = jt * 64 + s * 32;
        float acc[4] = {0.f, 0.f, 0.f, 0.f};
        #pragma unroll
        for (int mi = 0; mi < 2; mi++) {
            int r0 = mi * 16 + g;
            #pragma unroll
            for (int ni = 0; ni < 4; ni++) {
                int ch = h * 32 + ni * 8 + 2 * c;
                float q0 = sQC[ch], q1 = sQC[ch + 1];
                float2 kA = __ldg((const float2*)(g_kc + (size_t)(bN + jg0 + r0) * NDIM + ch));
                float2 kB = __ldg((const float2*)(g_kc + (size_t)(bN + jg0 + r0 + 8) * NDIM + ch));
                acc[mi * 2]     += (Dq[mi][ni][0] + q0) * (Dk[mi][ni][0] + kA.x)
                                 + (Dq[mi][ni][1] + q1) * (Dk[mi][ni][1] + kA.y);
                acc[mi * 2 + 1] += (Dq[mi][ni][2] + q0) * (Dk[mi][ni][2] + kB.x)
                                 + (Dq[mi][ni][3] + q1) * (Dk[mi][ni][3] + kB.y);
            }
        }
        #pragma unroll
        for (int t = 1; t <= 2; t <<= 1) {
            acc[0] += __shfl_xor_sync(0xffffffffu, acc[0], t);
            acc[1] += __shfl_xor_sync(0xffffffffu, acc[1], t);
            acc[2] += __shfl_xor_sync(0xffffffffu, acc[2], t);
            acc[3] += __shfl_xor_sync(0xffffffffu, acc[3], t);
        }
        if (c == 0) {
            sQK[h * 512 + jg0 + g]      = acc[0] * SCALE_F;
            sQK[h * 512 + jg0 + g + 8]  = acc[1] * SCALE_F;
            sQK[h * 512 + jg0 + 16 + g] = acc[2] * SCALE_F;
            sQK[h * 512 + jg0 + 24 + g] = acc[3] * SCALE_F;
        }
    }
    __syncthreads();

    // ---------------- Softmax: warp (s,h) handles half-row [s*256, s*256+256) ------
    float* srow = sQK + h * 512;
    {
        float m = -1e30f;
        for (int jj = s * 256 + lane; jj < s * 256 + 256; jj += 32)
            m = fmaxf(m, srow[jj]);
        #pragma unroll
        for (int off = 16; off > 0; off >>= 1) m = fmaxf(m, __shfl_xor_sync(0xffffffffu, m, off));
        if (lane == 0) sMax[s * 8 + h] = m;
    }
    __syncthreads();
    {
        float M = fmaxf(sMax[h], sMax[8 + h]);
        float ssum = 0.f;
        for (int jj = s * 256 + lane; jj < s * 256 + 256; jj += 32) {
            float p = __expf(srow[jj] - M);
            srow[jj] = p;
            ssum += p;
        }
        #pragma unroll
        for (int off = 16; off > 0; off >>= 1) ssum += __shfl_xor_sync(0xffffffffu, ssum, off);
        if (lane == 0) sSum[s * 8 + h] = ssum;
    }

    // ---------------- Phase 2: weighted edge context + vc context ----------------
    // alias sWq region: two 128x68 tiles (one per half)
    float* sE2 = sm;
    float ce0 = 0.f, ce1 = 0.f, cv = 0.f;
    for (int tt = 0; tt < 2; tt++) {
        __syncthreads();
        #pragma unroll
        for (int u = 0; u < 8; u++) {
            int idx = tid + u * 512;           // 0..4095 float4s
            int reg = idx >> 11;               // which half's tile
            int rem = idx & 2047;
            int row = rem >> 4, q = rem & 15;
            float4 v = *(const float4*)(edgeRowBase + (size_t)(reg * 256 + tt * 128 + row) * EDIM + q * 4);
            *(float4*)&sE2[reg * 8704 + row * 68 + q * 4] = v;
        }
        __syncthreads();

        const float* vcB = g_vc + (size_t)(bN + s * 256 + tt * 128) * NDIM + h * 32 + lane;
        const float* myE = sE2 + s * 8704;
        const float* arow = srow + s * 256 + tt * 128;
        #pragma unroll 4
        for (int j = 0; j < 128; j++) {
            float a = arow[j];
            float2 ev = *(const float2*)&myE[j * 68 + 2 * lane];
            ce0 += a * ev.x;
            ce1 += a * ev.y;
            cv  += a * vcB[(size_t)j * NDIM];
        }
    }

    // partial exchange: s=1 -> smem, s=0 combines + epilogue
    if (s == 1) {
        sP[(h * 32 + lane) * 3 + 0] = ce0;
        sP[(h * 32 + lane) * 3 + 1] = ce1;
        sP[(h * 32 + lane) * 3 + 2] = cv;
    }
    __syncthreads();
    if (s == 0) {
        ce0 += sP[(h * 32 + lane) * 3 + 0];
        ce1 += sP[(h * 32 + lane) * 3 + 1];
        cv  += sP[(h * 32 + lane) * 3 + 2];
        float inv = 1.f / (sSum[h] + sSum[8 + h]);
        #pragma unroll 4
        for (int dd = 0; dd < 32; dd++) {
            int ch = h * 32 + dd;
            float2 w2 = __ldg((const float2*)&Wev[ch * 64 + 2 * lane]);
            float part = w2.x * ce0 + w2.y * ce1;
            #pragma unroll
            for (int off = 16; off > 0; off >>= 1) part += __shfl_xor_sync(0xffffffffu, part, off);
            float cvd = __shfl_sync(0xffffffffu, cv, dd);
            if (lane == 0) sOut[ch] = (part + cvd) * inv;
        }
    }
    __syncthreads();
    if (tid < 256) out[(size_t)(bN + i) * NDIM + tid] = sOut[tid];
}

// =================================================================================
extern "C" void kernel_launch(void* const* d_in, const int* in_sizes, int n_in,
                              void* d_out, int out_size)
{
    const float* node = (const float*)d_in[0];
    const float* edge = (const float*)d_in[1];
    const float* Wnq  = (const float*)d_in[2];
    const float* bnq  = (const float*)d_in[3];
    const float* Wnk  = (const float*)d_in[4];
    const float* bnk  = (const float*)d_in[5];
    const float* Wnv  = (const float*)d_in[6];
    const float* bnv  = (const float*)d_in[7];
    const float* Weq  = (const float*)d_in[8];
    const float* beq  = (const float*)d_in[9];
    const float* Wek  = (const float*)d_in[10];
    const float* bek  = (const float*)d_in[11];
    const float* Wev  = (const float*)d_in[12];
    const float* bev  = (const float*)d_in[13];
    float* out = (float*)d_out;

    const int smemA = (8 * 257 + 64 * 260) * 4;      // 74784 B
    const int smemB = 53504 * 4;                     // 214016 B
    cudaFuncSetAttribute(node_proj_kernel, cudaFuncAttributeMaxDynamicSharedMemorySize, smemA);
    cudaFuncSetAttribute(main_attn_kernel, cudaFuncAttributeMaxDynamicSharedMemorySize, smemB);

    dim3 gridA(128, 3);
    node_proj_kernel<<<gridA, 256, smemA>>>(node, Wnq, bnq, Wnk, bnk, Wnv, bnv, beq, bek, bev);

    dim3 grid(N_SZ, B_SZ);
    main_attn_kernel<<<grid, 512, smemB>>>(edge, Weq, Wek, Wev, out);
}